// round 16
// baseline (speedup 1.0000x reference)
#include <cuda_runtime.h>
#include <cstdint>

typedef unsigned int uint;

// tcgen05 is arch-specific: only available in the sm_103a compilation pass.
#if defined(__CUDA_ARCH__) && defined(__CUDA_ARCH_FEAT_SM103_ALL)
#define TCG 1
#else
#define TCG 0
#endif

// =================== PTX helpers ===================
#if TCG
__device__ __forceinline__ uint elect_one_pred() {
    uint pred;
    asm volatile("{\n\t.reg .pred p;\n\telect.sync _|p, 0xFFFFFFFF;\n\t"
                 "selp.b32 %0, 1, 0, p;\n\t}" : "=r"(pred));
    return pred;
}
__device__ __forceinline__ uint smem_to_u32(const void* p) {
    uint a;
    asm("{ .reg .u64 t; cvta.to.shared.u64 t, %1; cvt.u32.u64 %0, t; }" : "=r"(a) : "l"(p));
    return a;
}
#define TCGEN05_ALLOC(smem_result_addr, nCols) \
    asm volatile("tcgen05.alloc.cta_group::1.sync.aligned.shared::cta.b32 [%0], %1;" \
        :: "r"((uint)(smem_result_addr)), "r"((uint)(nCols)) : "memory")
#define TCGEN05_DEALLOC(tmem_addr, nCols) \
    asm volatile("tcgen05.dealloc.cta_group::1.sync.aligned.b32 %0, %1;" \
        :: "r"(tmem_addr), "r"(nCols))
#define TCGEN05_RELINQUISH() \
    asm volatile("tcgen05.relinquish_alloc_permit.cta_group::1.sync.aligned;")
#define TCGEN05_WAIT_ST() asm volatile("tcgen05.wait::st.sync.aligned;" ::: "memory")
#define TCGEN05_WAIT_LD() asm volatile("tcgen05.wait::ld.sync.aligned;" ::: "memory")
#define TCGEN05_FENCE_AFTER() asm volatile("tcgen05.fence::after_thread_sync;" ::: "memory")
#define TCGEN05_FENCE_BEFORE() asm volatile("tcgen05.fence::before_thread_sync;" ::: "memory")
#define TCGEN05_COMMIT(mbar) \
    asm volatile("tcgen05.commit.cta_group::1.mbarrier::arrive::one.shared::cluster.b64 [%0];" \
        :: "r"((uint)(mbar)) : "memory")
#define MBARRIER_INIT(mbar, cnt) \
    asm volatile("mbarrier.init.shared.b64 [%0], %1;" :: "r"((uint)(mbar)), "r"((uint)(cnt)) : "memory")
#define MBARRIER_INVAL(mbar) \
    asm volatile("mbarrier.inval.shared.b64 [%0];" :: "r"((uint)(mbar)) : "memory")
#define MBARRIER_WAIT_PARITY(mbar, parity) do { \
    uint _m = (uint)(mbar), _p = (uint)(parity), _d; \
    asm volatile("{\n\t.reg .pred p;\n\t" \
        "mbarrier.try_wait.parity.acquire.cta.shared::cta.b64 p, [%1], %2;\n\t" \
        "selp.b32 %0, 1, 0, p;\n\t}" : "=r"(_d) : "r"(_m), "r"(_p) : "memory"); \
    if (!_d) { \
        asm volatile("{\n\t.reg .pred P1;\n\t" \
            "WAIT_LOOP_%=:\n\t" \
            "mbarrier.try_wait.parity.acquire.cta.shared::cta.b64 P1, [%0], %1, 0x989680;\n\t" \
            "@P1 bra.uni WAIT_DONE_%=;\n\t" \
            "bra.uni WAIT_LOOP_%=;\n\t" \
            "WAIT_DONE_%=:\n\t}" :: "r"(_m), "r"(_p) : "memory"); \
    } \
} while (0)
#define TCGEN05_MMA_F16(d_tmem, a_tmem, b_desc, idesc, enable_d) do { \
    uint _en = (enable_d) ? 1u : 0u; uint _z = 0u; \
    asm volatile("{\n\t.reg .pred p;\n\tsetp.ne.u32 p, %6, 0;\n\t" \
        "tcgen05.mma.cta_group::1.kind::f16 [%0], [%1], %2, %3, {%4, %4, %4, %4}, p;\n\t}" \
        :: "r"(d_tmem), "r"(a_tmem), "l"(b_desc), "r"(idesc), "r"(_z), "r"(_z), "r"(_en) \
        : "memory"); \
} while (0)
#define TCGEN05_ST_X16(tmem_addr, r) \
    asm volatile("tcgen05.st.sync.aligned.32x32b.x16.b32 [%0], " \
        "{%1,%2,%3,%4,%5,%6,%7,%8,%9,%10,%11,%12,%13,%14,%15,%16};" \
        :: "r"(tmem_addr), \
           "r"((r)[0]),"r"((r)[1]),"r"((r)[2]),"r"((r)[3]),"r"((r)[4]),"r"((r)[5]),"r"((r)[6]),"r"((r)[7]), \
           "r"((r)[8]),"r"((r)[9]),"r"((r)[10]),"r"((r)[11]),"r"((r)[12]),"r"((r)[13]),"r"((r)[14]),"r"((r)[15]) \
        : "memory")
#define TCGEN05_ST_X32(tmem_addr, r) \
    asm volatile("tcgen05.st.sync.aligned.32x32b.x32.b32 [%0], " \
        "{%1,%2,%3,%4,%5,%6,%7,%8,%9,%10,%11,%12,%13,%14,%15,%16," \
        " %17,%18,%19,%20,%21,%22,%23,%24,%25,%26,%27,%28,%29,%30,%31,%32};" \
        :: "r"(tmem_addr), \
           "r"((r)[0]),"r"((r)[1]),"r"((r)[2]),"r"((r)[3]),"r"((r)[4]),"r"((r)[5]),"r"((r)[6]),"r"((r)[7]), \
           "r"((r)[8]),"r"((r)[9]),"r"((r)[10]),"r"((r)[11]),"r"((r)[12]),"r"((r)[13]),"r"((r)[14]),"r"((r)[15]), \
           "r"((r)[16]),"r"((r)[17]),"r"((r)[18]),"r"((r)[19]),"r"((r)[20]),"r"((r)[21]),"r"((r)[22]),"r"((r)[23]), \
           "r"((r)[24]),"r"((r)[25]),"r"((r)[26]),"r"((r)[27]),"r"((r)[28]),"r"((r)[29]),"r"((r)[30]),"r"((r)[31]) \
        : "memory")
#define TCGEN05_LD_X32(r, tmem_addr) \
    asm volatile("tcgen05.ld.sync.aligned.32x32b.x32.b32 " \
        "{%0,%1,%2,%3,%4,%5,%6,%7,%8,%9,%10,%11,%12,%13,%14,%15," \
        " %16,%17,%18,%19,%20,%21,%22,%23,%24,%25,%26,%27,%28,%29,%30,%31}, [%32];" \
        : "=r"((r)[0]),"=r"((r)[1]),"=r"((r)[2]),"=r"((r)[3]),"=r"((r)[4]),"=r"((r)[5]),"=r"((r)[6]),"=r"((r)[7]), \
          "=r"((r)[8]),"=r"((r)[9]),"=r"((r)[10]),"=r"((r)[11]),"=r"((r)[12]),"=r"((r)[13]),"=r"((r)[14]),"=r"((r)[15]), \
          "=r"((r)[16]),"=r"((r)[17]),"=r"((r)[18]),"=r"((r)[19]),"=r"((r)[20]),"=r"((r)[21]),"=r"((r)[22]),"=r"((r)[23]), \
          "=r"((r)[24]),"=r"((r)[25]),"=r"((r)[26]),"=r"((r)[27]),"=r"((r)[28]),"=r"((r)[29]),"=r"((r)[30]),"=r"((r)[31]) \
        : "r"(tmem_addr))
#endif  // TCG

// SW128 smem descriptor (Blackwell, LBO=1, SBO=64) — verified constants
static constexpr uint64_t SMEM_DESC_BASE_SW128 =
    (uint64_t(2) << 61) | (uint64_t(1) << 46) | (uint64_t(64) << 32) | (uint64_t(1) << 16);
#define MAKE_SMEM_DESC(addr) (SMEM_DESC_BASE_SW128 | ((uint64_t)((addr) >> 4) & 0x3FFF))

// idesc kind::f16: dtype F32(1<<4) | atype BF16(1<<7) | btype BF16(1<<10) | (N/8)<<17 | (M/16)<<24
static constexpr uint IDESC2 = 0x490u | (8u  << 17) | (8u << 24);   // M=128, N=64
static constexpr uint IDESC3 = 0x490u | (16u << 17) | (8u << 24);   // M=128, N=128

// =================== static device scratch ===================
__device__ float g_wscale[4];
__device__ float g_w1q[32*3*3*3];
__device__ uint  g_w2f[4608];     // conv2 weights, legacy IMMA A-frag order (fallback path)
__device__ uint  g_w3f[18432];    // conv3 weights, legacy IMMA A-frag order (fallback path)
__device__ uint4 g_w2b[2560];     // conv2 weights bf16, SW128 blocked-atom layout (tcgen05)
__device__ uint4 g_w3b[9216];     // conv3 weights bf16, SW128 blocked-atom layout (tcgen05)
__device__ uint  g_wcp[10*32];
__device__ uint4 g_h1[32*112*112*32/16];
__device__ uint4 g_h2[32*56*56*64/16];
__device__ uint4 g_h3[32*28*28*128/16];

// ---------------- shared helpers ----------------
__device__ __forceinline__ void mma_s8(int* c, uint a0, uint a1, uint a2, uint a3,
                                       uint b0, uint b1) {
    asm volatile(
        "mma.sync.aligned.m16n8k32.row.col.s32.s8.s8.s32 "
        "{%0,%1,%2,%3}, {%4,%5,%6,%7}, {%8,%9}, {%0,%1,%2,%3};\n"
        : "+r"(c[0]), "+r"(c[1]), "+r"(c[2]), "+r"(c[3])
        : "r"(a0), "r"(a1), "r"(a2), "r"(a3), "r"(b0), "r"(b1));
}
// code(0..3) -> bf16 pair via byte_perm LUT
__device__ __forceinline__ void expand4(uint w, uint& lo, uint& hi) {
    const uint L = 0x40008000u;   // lo bytes of bf16(0..3)
    const uint H = 0x40403F00u;   // hi bytes of bf16(0..3)
    uint c0 = w & 3u, c1 = (w >> 8) & 3u, c2 = (w >> 16) & 3u, c3 = (w >> 24) & 3u;
    lo = __byte_perm(L, H, c0 * 0x11u + c1 * 0x1100u + 0x4040u);
    hi = __byte_perm(L, H, c2 * 0x11u + c3 * 0x1100u + 0x4040u);
}
__device__ __forceinline__ uint enc_tern(int q) {       // -1/0/1 -> bf16 bits
    return q > 0 ? 0x3F80u : (q < 0 ? 0xBF80u : 0u);
}
// byte offset in SW128 blocked-atom B tile: row=n (oc), col=k (bf16), N8 = N/8 atoms per k-block
__device__ __forceinline__ uint b_off(int n, int k, int N8) {
    uint off = (uint)((n >> 3) + (k >> 6) * N8) * 1024u + (uint)(n & 7) * 128u + (uint)(k & 63) * 2u;
    return off ^ ((off >> 3) & 0x70u);
}

// =================== kernel 0: per-tensor max-abs weight scales ===================
__global__ void k_scales(const float* __restrict__ w1, const float* __restrict__ w2,
                         const float* __restrict__ w3, const float* __restrict__ wc) {
    const float* ptrs[4] = {w1, w2, w3, wc};
    const int    ns[4]   = {864, 18432, 73728, 1280};
    int r = blockIdx.x;
    const float* w = ptrs[r];
    int n = ns[r];
    float m = 0.f;
    for (int i = threadIdx.x; i < n; i += blockDim.x) m = fmaxf(m, fabsf(w[i]));
    __shared__ float s[256];
    s[threadIdx.x] = m;
    __syncthreads();
    for (int o = 128; o > 0; o >>= 1) {
        if (threadIdx.x < o) s[threadIdx.x] = fmaxf(s[threadIdx.x], s[threadIdx.x + o]);
        __syncthreads();
    }
    if (threadIdx.x == 0) g_wscale[r] = fmaxf(s[0], 1e-8f);
}

// =================== kernel 1: quantize + pack weights (both encodings) ===================
__global__ void k_pack(const float* __restrict__ w1, const float* __restrict__ w2,
                       const float* __restrict__ w3, const float* __restrict__ wc) {
    int i = blockIdx.x * blockDim.x + threadIdx.x;
    if (i < 864) {
        float s = g_wscale[0];
        g_w1q[i] = rintf(__fdiv_rn(w1[i], s)) * s;
    } else if (i < 864 + 4608) {
        // conv2 IMMA A-frag
        int k = i - 864;
        float s = g_wscale[1];
        int e = k >> 2, r = k & 3;
        int lane = e & 31, tap = (e >> 5) % 9, m = e / 288;
        int oc  = m * 16 + (lane >> 2) + (r & 1) * 8;
        int ic0 = (r >> 1) * 16 + (lane & 3) * 4;
        int ty = tap / 3, tx = tap % 3;
        uint pk = 0;
        #pragma unroll
        for (int kk = 0; kk < 4; kk++) {
            int q = (int)rintf(__fdiv_rn(w2[((oc * 32 + ic0 + kk) * 3 + ty) * 3 + tx], s));
            pk |= ((uint)(unsigned char)(signed char)q) << (8 * kk);
        }
        g_w2f[k] = pk;
    } else if (i < 864 + 4608 + 18432) {
        // conv3 IMMA A-frag
        int k = i - (864 + 4608);
        float s = g_wscale[2];
        int e = k >> 2, r = k & 3;
        int lane = e & 31;
        int kc  = (e >> 5) & 1;
        int tap = (e >> 6) % 9;
        int m   = e / 576;
        int oc  = m * 16 + (lane >> 2) + (r & 1) * 8;
        int ic0 = kc * 32 + (r >> 1) * 16 + (lane & 3) * 4;
        int ty = tap / 3, tx = tap % 3;
        uint pk = 0;
        #pragma unroll
        for (int kk = 0; kk < 4; kk++) {
            int q = (int)rintf(__fdiv_rn(w3[((oc * 64 + ic0 + kk) * 3 + ty) * 3 + tx], s));
            pk |= ((uint)(unsigned char)(signed char)q) << (8 * kk);
        }
        g_w3f[k] = pk;
    } else if (i < 864 + 4608 + 18432 + 320) {
        int k = i - (864 + 4608 + 18432);
        float s = g_wscale[3];
        int oc = k / 32, j = k % 32;
        uint pk = 0;
        #pragma unroll
        for (int kk = 0; kk < 4; kk++) {
            int q = (int)rintf(__fdiv_rn(wc[oc * 128 + 4 * j + kk], s));
            pk |= ((uint)(unsigned char)(signed char)q) << (8 * kk);
        }
        g_wcp[k] = pk;
    } else if (i < 864 + 4608 + 18432 + 320 + 10240) {
        // conv2 bf16 SW128 (K2 = 288, padded to 320; N=64 -> 10240 uints)
        int idx = i - (864 + 4608 + 18432 + 320);
        float s = g_wscale[1];
        int oc = idx / 160, kp = idx % 160, k0 = 2 * kp;
        uint word = 0;
        #pragma unroll
        for (int h = 0; h < 2; h++) {
            int k = k0 + h;
            uint e = 0;
            if (k < 288) {
                int tap = k / 32, ic = k % 32, ty = tap / 3, tx = tap % 3;
                e = enc_tern((int)rintf(__fdiv_rn(w2[((oc * 32 + ic) * 3 + ty) * 3 + tx], s)));
            }
            word |= e << (16 * h);
        }
        ((uint*)g_w2b)[b_off(oc, k0, 8) >> 2] = word;
    } else if (i < 864 + 4608 + 18432 + 320 + 10240 + 36864) {
        // conv3 bf16 SW128 (K3 = 576, exact; N=128 -> 36864 uints)
        int idx = i - (864 + 4608 + 18432 + 320 + 10240);
        float s = g_wscale[2];
        int oc = idx / 288, kp = idx % 288, k0 = 2 * kp;
        uint word = 0;
        #pragma unroll
        for (int h = 0; h < 2; h++) {
            int k = k0 + h;
            int tap = k / 64, ic = k % 64, ty = tap / 3, tx = tap % 3;
            uint e = enc_tern((int)rintf(__fdiv_rn(w3[((oc * 64 + ic) * 3 + ty) * 3 + tx], s)));
            word |= e << (16 * h);
        }
        ((uint*)g_w3b)[b_off(oc, k0, 16) >> 2] = word;
    }
}

// =================== kernel 2: conv1 (fp32) + quant + pool ===================
__global__ __launch_bounds__(256) void k_conv1(const float* __restrict__ x,
                                               const float* __restrict__ a1) {
    __shared__ float s_in[3*34*34];
    __shared__ float s_w[864];
    int b  = blockIdx.z;
    int Y0 = blockIdx.y * 16, X0 = blockIdx.x * 16;

    for (int i = threadIdx.x; i < 864; i += 256) s_w[i] = g_w1q[i];
    for (int i = threadIdx.x; i < 3*34*34; i += 256) {
        int ic = i / 1156, rem = i % 1156, r = rem / 34, c = rem % 34;
        int gy = 2*Y0 - 1 + r, gx = 2*X0 - 1 + c;
        float v = 0.f;
        if ((unsigned)gy < 224u && (unsigned)gx < 224u)
            v = x[((b*3 + ic)*224 + gy)*224 + gx];
        s_in[i] = v;
    }
    __syncthreads();

    int sy = threadIdx.x >> 4, sx = threadIdx.x & 15;
    float p[3][4][4];
    #pragma unroll
    for (int ic = 0; ic < 3; ic++)
        #pragma unroll
        for (int u = 0; u < 4; u++)
            #pragma unroll
            for (int v = 0; v < 4; v++)
                p[ic][u][v] = s_in[ic*1156 + (2*sy + u)*34 + (2*sx + v)];

    float alpha = a1[0];
    float qs = __fdiv_rn(alpha, 3.0f);
    uint* h1u = (uint*)g_h1;
    int pixbase = ((b*112 + (Y0 + sy))*112 + (X0 + sx)) * 8;

    #pragma unroll 1
    for (int og = 0; og < 8; og++) {
        uint pk = 0;
        #pragma unroll
        for (int oo = 0; oo < 4; oo++) {
            int oc = og*4 + oo;
            float a00 = 0.f, a01 = 0.f, a10 = 0.f, a11 = 0.f;
            #pragma unroll
            for (int ic = 0; ic < 3; ic++)
                #pragma unroll
                for (int ty = 0; ty < 3; ty++)
                    #pragma unroll
                    for (int tx = 0; tx < 3; tx++) {
                        float w = s_w[oc*27 + ic*9 + ty*3 + tx];
                        a00 = fmaf(w, p[ic][ty  ][tx  ], a00);
                        a01 = fmaf(w, p[ic][ty  ][tx+1], a01);
                        a10 = fmaf(w, p[ic][ty+1][tx  ], a10);
                        a11 = fmaf(w, p[ic][ty+1][tx+1], a11);
                    }
            float v = fmaxf(fmaxf(a00, a01), fmaxf(a10, a11));
            float y = fminf(fmaxf(v, 0.f), alpha);
            uint code = (uint)(int)rintf(__fdiv_rn(y, qs));
            pk |= code << (8*oo);
        }
        h1u[pixbase + og] = pk;
    }
}

// =================== fallback kernels (legacy IMMA) — empty in sm_103a pass ===================
__global__ __launch_bounds__(256) void k_mma2(const float* __restrict__ a_prev,
                                              const float* __restrict__ a_cur) {
#if !TCG && defined(__CUDA_ARCH__)
    __shared__ uint4 s4[4*114*3];
    uint* sw = (uint*)s4;
    int Y = blockIdx.x, b = blockIdx.y;
    int tid = threadIdx.x;

    for (int j = tid; j < 912; j += 256) {
        int row = j / 228, rem = j % 228, pix = rem >> 1, half = rem & 1;
        int gy = 2*Y - 1 + row, gx = pix - 1;
        uint4 v = make_uint4(0u,0u,0u,0u);
        if ((unsigned)gy < 112u && (unsigned)gx < 112u)
            v = g_h1[((b*112 + gy)*112 + gx)*2 + half];
        s4[(row*114 + pix)*3 + half] = v;
    }
    __syncthreads();

    int warp = tid >> 5, lane = tid & 31;
    int xh = warp & 1, m = warp >> 1;
    int g = lane >> 2, q = lane & 3;

    int acc[2][7][4];
    #pragma unroll
    for (int y = 0; y < 2; y++)
        #pragma unroll
        for (int nt = 0; nt < 7; nt++)
            #pragma unroll
            for (int k = 0; k < 4; k++) acc[y][nt][k] = 0;

    const uint4* wf = (const uint4*)g_w2f;
    #pragma unroll 1
    for (int tap = 0; tap < 9; tap++) {
        uint4 wv = wf[(m*9 + tap)*32 + lane];
        int ty = tap / 3, tx = tap % 3;
        #pragma unroll
        for (int y = 0; y < 2; y++) {
            int rowbase = (y + ty)*114;
            #pragma unroll
            for (int nt = 0; nt < 7; nt++) {
                int pix = xh*56 + nt*8 + g + tx;
                int w0 = (rowbase + pix)*12 + q;
                uint b0 = sw[w0], b1 = sw[w0 + 4];
                mma_s8(acc[y][nt], wv.x, wv.y, wv.z, wv.w, b0, b1);
            }
        }
    }

    float scale = g_wscale[1] * __fdiv_rn(a_prev[0], 3.0f);
    float alpha = a_cur[0];
    float qs = __fdiv_rn(alpha, 3.0f);
    char* out = (char*)g_h2;
    #pragma unroll
    for (int nt = 0; nt < 7; nt++) {
        int v0 = max(max(acc[0][nt][0], acc[0][nt][1]), max(acc[1][nt][0], acc[1][nt][1]));
        int v1 = max(max(acc[0][nt][2], acc[0][nt][3]), max(acc[1][nt][2], acc[1][nt][3]));
        int X = xh*28 + nt*4 + q;
        int base = ((b*56 + Y)*56 + X)*64 + m*16 + g;
        float y0 = fminf(fmaxf(scale*(float)v0, 0.f), alpha);
        float y1 = fminf(fmaxf(scale*(float)v1, 0.f), alpha);
        out[base]     = (char)(int)rintf(__fdiv_rn(y0, qs));
        out[base + 8] = (char)(int)rintf(__fdiv_rn(y1, qs));
    }
#endif
}

__global__ __launch_bounds__(256) void k_mma3(const float* __restrict__ a_prev,
                                              const float* __restrict__ a_cur) {
#if !TCG && defined(__CUDA_ARCH__)
    __shared__ uint4 s4[4*58*5];
    uint* sw = (uint*)s4;
    int Y = blockIdx.x, b = blockIdx.y;
    int tid = threadIdx.x;

    for (int j = tid; j < 928; j += 256) {
        int row = j / 232, rem = j % 232, pix = rem >> 2, qq = rem & 3;
        int gy = 2*Y - 1 + row, gx = pix - 1;
        uint4 v = make_uint4(0u,0u,0u,0u);
        if ((unsigned)gy < 56u && (unsigned)gx < 56u)
            v = g_h2[((b*56 + gy)*56 + gx)*4 + qq];
        s4[(row*58 + pix)*5 + qq] = v;
    }
    __syncthreads();

    int warp = tid >> 5, lane = tid & 31;
    int m = warp;
    int g = lane >> 2, q = lane & 3;

    int acc[2][7][4];
    #pragma unroll
    for (int y = 0; y < 2; y++)
        #pragma unroll
        for (int nt = 0; nt < 7; nt++)
            #pragma unroll
            for (int k = 0; k < 4; k++) acc[y][nt][k] = 0;

    const uint4* wf = (const uint4*)g_w3f;
    #pragma unroll 1
    for (int tap = 0; tap < 9; tap++) {
        int ty = tap / 3, tx = tap % 3;
        #pragma unroll
        for (int kc = 0; kc < 2; kc++) {
            uint4 wv = wf[((m*9 + tap)*2 + kc)*32 + lane];
            #pragma unroll
            for (int y = 0; y < 2; y++) {
                int rowbase = (y + ty)*58;
                #pragma unroll
                for (int nt = 0; nt < 7; nt++) {
                    int pix = nt*8 + g + tx;
                    int w0 = (rowbase + pix)*20 + kc*8 + q;
                    uint b0 = sw[w0], b1 = sw[w0 + 4];
                    mma_s8(acc[y][nt], wv.x, wv.y, wv.z, wv.w, b0, b1);
                }
            }
        }
    }

    float scale = g_wscale[2] * __fdiv_rn(a_prev[0], 3.0f);
    float alpha = a_cur[0];
    float qs = __fdiv_rn(alpha, 3.0f);
    char* out = (char*)g_h3;
    #pragma unroll
    for (int nt = 0; nt < 7; nt++) {
        int v0 = max(max(acc[0][nt][0], acc[0][nt][1]), max(acc[1][nt][0], acc[1][nt][1]));
        int v1 = max(max(acc[0][nt][2], acc[0][nt][3]), max(acc[1][nt][2], acc[1][nt][3]));
        int X = nt*4 + q;
        int base = ((b*28 + Y)*28 + X)*128 + m*16 + g;
        float y0 = fminf(fmaxf(scale*(float)v0, 0.f), alpha);
        float y1 = fminf(fmaxf(scale*(float)v1, 0.f), alpha);
        out[base]     = (char)(int)rintf(__fdiv_rn(y0, qs));
        out[base + 8] = (char)(int)rintf(__fdiv_rn(y1, qs));
    }
#endif
}

// =================== tcgen05 kernels — empty in non-a pass ===================
// conv2: M=128 px (1 pooled row × 64 pre-pool x), N=64 oc, K=288. Persistent, 1 CTA/SM.
__global__ __launch_bounds__(128) void k_t2(const float* __restrict__ a_prev,
                                            const float* __restrict__ a_cur) {
#if TCG
    extern __shared__ char smem[];
    uint sb = smem_to_u32(smem);
    int tid = threadIdx.x, wid = tid >> 5, lane = tid & 31;
    uint brel = ((sb + 8512u + 1023u) & ~1023u) - sb;
    uint* Bp = (uint*)(smem + brel);
    char* codes = smem + 64;

    for (int i = tid; i < 10240; i += 128) Bp[i] = ((const uint*)g_w2b)[i];

    if (wid == 0) { TCGEN05_ALLOC(sb + 0, 256); TCGEN05_RELINQUISH(); }
    if (tid == 0) MBARRIER_INIT(sb + 8, 1);
    __syncthreads();
    uint tmem;
    asm volatile("ld.shared.b32 %0, [%1];" : "=r"(tmem) : "r"(sb + 0));
    uint64_t bdesc0 = MAKE_SMEM_DESC(sb + brel);
    uint warp_off = (uint)wid << 21;

    float scale = g_wscale[1] * __fdiv_rn(a_prev[0], 3.0f);
    float alpha = a_cur[0];
    float qs = __fdiv_rn(alpha, 3.0f);

    int ph = 0;
    for (int t = blockIdx.x; t < 3584; t += 148) {
        int b = t / 112, r2 = t % 112, Yp = r2 >> 1, X0 = (r2 & 1) * 48;
        __syncthreads();
        for (int i = tid; i < 528; i += 128) {
            int r = i / 132, rem = i % 132, cc = rem >> 1, half = rem & 1;
            int gy = 2*Yp - 1 + r, gx = X0 - 1 + cc;
            uint4 v = make_uint4(0u,0u,0u,0u);
            if ((unsigned)gy < 112u && (unsigned)gx < 112u)
                v = g_h1[((b*112 + gy)*112 + gx)*2 + half];
            *(uint4*)(codes + (r*66 + cc)*32 + half*16) = v;
        }
        __syncthreads();
        {
            int u = tid >> 2, c = tid & 3;
            int r_l = c >> 1, x_l = 2*u + (c & 1);
            #pragma unroll 1
            for (int tap = 0; tap < 9; tap++) {
                int ty = tap / 3, tx = tap % 3;
                const uint* src = (const uint*)(codes + ((r_l + ty)*66 + (x_l + tx))*32);
                uint rg[16];
                #pragma unroll
                for (int j = 0; j < 8; j++) expand4(src[j], rg[2*j], rg[2*j+1]);
                TCGEN05_ST_X16(tmem + tap*16 + warp_off, rg);
            }
            TCGEN05_WAIT_ST();
        }
        __syncthreads();
        if (wid == 0) {
            if (elect_one_pred()) {
                #pragma unroll 1
                for (int s = 0; s < 18; s++) {
                    uint64_t bd = bdesc0 + (uint64_t)((s & 3)*2 + (s >> 2)*512);
                    TCGEN05_MMA_F16(tmem + 144, tmem + s*8, bd, IDESC2, s > 0);
                }
                TCGEN05_COMMIT(sb + 8);
            }
        }
        MBARRIER_WAIT_PARITY(sb + 8, ph);
        ph ^= 1;
        TCGEN05_FENCE_AFTER();
        {
            uint d[64];
            TCGEN05_LD_X32(d,      tmem + 144);
            TCGEN05_LD_X32(d + 32, tmem + 144 + 32);
            TCGEN05_WAIT_LD();
            TCGEN05_FENCE_BEFORE();
            uint pk[16];
            #pragma unroll
            for (int j = 0; j < 16; j++) pk[j] = 0;
            #pragma unroll
            for (int j = 0; j < 64; j++) {
                float v = __uint_as_float(d[j]);
                v = fmaxf(v, __shfl_xor_sync(0xffffffffu, v, 1));
                v = fmaxf(v, __shfl_xor_sync(0xffffffffu, v, 2));
                float y = fminf(fmaxf(scale * v, 0.f), alpha);
                uint code = (uint)(int)rintf(__fdiv_rn(y, qs));
                pk[j >> 2] |= code << (8*(j & 3));
            }
            if ((lane & 3) == 0) {
                int u = (wid*32 + lane) >> 2;
                int Xp = (X0 >> 1) + u;
                uint4* dst = (uint4*)((char*)g_h2 + ((size_t)((b*56 + Yp)*56 + Xp)) * 64);
                dst[0] = make_uint4(pk[0], pk[1], pk[2], pk[3]);
                dst[1] = make_uint4(pk[4], pk[5], pk[6], pk[7]);
                dst[2] = make_uint4(pk[8], pk[9], pk[10], pk[11]);
                dst[3] = make_uint4(pk[12], pk[13], pk[14], pk[15]);
            }
        }
    }
    __syncthreads();
    if (tid == 0) MBARRIER_INVAL(sb + 8);
    __syncthreads();
    if (wid == 0) TCGEN05_DEALLOC(tmem, 256);
#endif
}

// conv3: M=128 px (112 valid), N=128 oc, K=576. Persistent, 1 CTA/SM.
__global__ __launch_bounds__(128) void k_t3(const float* __restrict__ a_prev,
                                            const float* __restrict__ a_cur) {
#if TCG
    extern __shared__ char smem[];
    uint sb = smem_to_u32(smem);
    int tid = threadIdx.x, wid = tid >> 5, lane = tid & 31;
    uint brel = ((sb + 14912u + 1023u) & ~1023u) - sb;
    uint4* Bp = (uint4*)(smem + brel);
    char* codes = smem + 64;

    for (int i = tid; i < 9216; i += 128) Bp[i] = g_w3b[i];

    if (wid == 0) { TCGEN05_ALLOC(sb + 0, 512); TCGEN05_RELINQUISH(); }
    if (tid == 0) MBARRIER_INIT(sb + 8, 1);
    __syncthreads();
    uint tmem;
    asm volatile("ld.shared.b32 %0, [%1];" : "=r"(tmem) : "r"(sb + 0));
    uint64_t bdesc0 = MAKE_SMEM_DESC(sb + brel);
    uint warp_off = (uint)wid << 21;

    float scale = g_wscale[2] * __fdiv_rn(a_prev[0], 3.0f);
    float alpha = a_cur[0];
    float qs = __fdiv_rn(alpha, 3.0f);

    int ph = 0;
    for (int t = blockIdx.x; t < 896; t += 148) {
        int b = t / 28, Yp = t % 28;
        __syncthreads();
        for (int i = tid; i < 928; i += 128) {
            int r = i / 232, rem = i % 232, cc = rem >> 2, qq = rem & 3;
            int gy = 2*Yp - 1 + r, gx = cc - 1;
            uint4 v = make_uint4(0u,0u,0u,0u);
            if ((unsigned)gy < 56u && (unsigned)gx < 56u)
                v = g_h2[((b*56 + gy)*56 + gx)*4 + qq];
            *(uint4*)(codes + (r*58 + cc)*64 + qq*16) = v;
        }
        __syncthreads();
        {
            int u = tid >> 2, c = tid & 3;
            if (u > 27) u = 27;
            int r_l = c >> 1, x_l = 2*u + (c & 1);
            #pragma unroll 1
            for (int tap = 0; tap < 9; tap++) {
                int ty = tap / 3, tx = tap % 3;
                const uint* src = (const uint*)(codes + ((r_l + ty)*58 + (x_l + tx))*64);
                uint rg[32];
                #pragma unroll
                for (int j = 0; j < 16; j++) expand4(src[j], rg[2*j], rg[2*j+1]);
                TCGEN05_ST_X32(tmem + tap*32 + warp_off, rg);
            }
            TCGEN05_WAIT_ST();
        }
        __syncthreads();
        if (wid == 0) {
            if (elect_one_pred()) {
                #pragma unroll 1
                for (int s = 0; s < 36; s++) {
                    uint64_t bd = bdesc0 + (uint64_t)((s & 3)*2 + (s >> 2)*1024);
                    TCGEN05_MMA_F16(tmem + 288, tmem + s*8, bd, IDESC3, s > 0);
                }
                TCGEN05_COMMIT(sb + 8);
            }
        }
        MBARRIER_WAIT_PARITY(sb + 8, ph);
        ph ^= 1;
        TCGEN05_FENCE_AFTER();
        {
            int u = (wid*32 + lane) >> 2;
            bool act = ((lane & 3) == 0) && (u < 28);
            size_t bytebase = ((size_t)((b*28 + Yp)*28 + (u < 28 ? u : 0))) * 128;
            #pragma unroll 1
            for (int ch = 0; ch < 4; ch++) {
                uint d[32];
                TCGEN05_LD_X32(d, tmem + 288 + 32*ch);
                TCGEN05_WAIT_LD();
                uint pk[8];
                #pragma unroll
                for (int j = 0; j < 8; j++) pk[j] = 0;
                #pragma unroll
                for (int j = 0; j < 32; j++) {
                    float v = __uint_as_float(d[j]);
                    v = fmaxf(v, __shfl_xor_sync(0xffffffffu, v, 1));
                    v = fmaxf(v, __shfl_xor_sync(0xffffffffu, v, 2));
                    float y = fminf(fmaxf(scale * v, 0.f), alpha);
                    uint code = (uint)(int)rintf(__fdiv_rn(y, qs));
                    pk[j >> 2] |= code << (8*(j & 3));
                }
                if (act) {
                    uint4* dst = (uint4*)((char*)g_h3 + bytebase + 32*ch);
                    dst[0] = make_uint4(pk[0], pk[1], pk[2], pk[3]);
                    dst[1] = make_uint4(pk[4], pk[5], pk[6], pk[7]);
                }
            }
            TCGEN05_FENCE_BEFORE();
        }
    }
    __syncthreads();
    if (tid == 0) MBARRIER_INVAL(sb + 8);
    __syncthreads();
    if (wid == 0) TCGEN05_DEALLOC(tmem, 512);
#endif
}

// =================== kernel 5: global amax pool + 1x1 ternary classifier ===================
__global__ void k_cls(const float* __restrict__ a3, float* __restrict__ out) {
    __shared__ uint s_part[4][32];
    __shared__ uint s_max[32];
    int b = blockIdx.x, t = threadIdx.x;
    const uint* h3u = (const uint*)g_h3;
    int quarter = t >> 5, ci = t & 31;
    uint m = 0;
    int p0 = quarter * 196;
    for (int p = p0; p < p0 + 196; p++)
        m = __vmaxu4(m, h3u[(b*784 + p)*32 + ci]);
    s_part[quarter][ci] = m;
    __syncthreads();
    if (t < 32)
        s_max[t] = __vmaxu4(__vmaxu4(s_part[0][t], s_part[1][t]),
                            __vmaxu4(s_part[2][t], s_part[3][t]));
    __syncthreads();
    if (t < 10) {
        int acc = 0;
        #pragma unroll
        for (int j = 0; j < 32; j++)
            acc = __dp4a((int)s_max[j], (int)g_wcp[t*32 + j], acc);
        float scale = g_wscale[3] * __fdiv_rn(a3[0], 3.0f);
        out[b*10 + t] = scale * (float)acc;
    }
}

// =================== launch ===================
extern "C" void kernel_launch(void* const* d_in, const int* in_sizes, int n_in,
                              void* d_out, int out_size) {
    const float* x  = (const float*)d_in[0];
    const float* w1 = (const float*)d_in[1];
    const float* w2 = (const float*)d_in[2];
    const float* w3 = (const float*)d_in[3];
    const float* wc = (const float*)d_in[4];
    const float* a1 = (const float*)d_in[5];
    const float* a2 = (const float*)d_in[6];
    const float* a3 = (const float*)d_in[7];
    float* out = (float*)d_out;

    const int SMEM_T2 = 8512 + 1024 + 40960;     // 50496
    const int SMEM_T3 = 14912 + 1024 + 147456;   // 163392
    cudaFuncSetAttribute(k_t2, cudaFuncAttributeMaxDynamicSharedMemorySize, SMEM_T2);
    cudaFuncSetAttribute(k_t3, cudaFuncAttributeMaxDynamicSharedMemorySize, SMEM_T3);

    k_scales<<<4, 256>>>(w1, w2, w3, wc);
    k_pack<<<(71328 + 255)/256, 256>>>(w1, w2, w3, wc);
    k_conv1<<<dim3(7, 7, 32), 256>>>(x, a1);        // 112x112x32 pooled codes

    // conv2/conv3: exactly one of each pair has a non-empty body per target.
    k_mma2<<<dim3(56, 32), 256>>>(a1, a2);          // fallback (non-a pass)
    k_t2<<<148, 128, SMEM_T2>>>(a1, a2);            // tcgen05 (sm_103a pass)
    k_mma3<<<dim3(28, 32), 256>>>(a2, a3);          // fallback
    k_t3<<<148, 128, SMEM_T3>>>(a2, a3);            // tcgen05

    k_cls<<<32, 128>>>(a3, out);
}

// round 17
// speedup vs baseline: 1.0061x; 1.0061x over previous
#include <cuda_runtime.h>
#include <cstdint>

typedef unsigned int uint;

// tcgen05 is arch-specific: only available in the sm_103a compilation pass.
#if defined(__CUDA_ARCH__) && defined(__CUDA_ARCH_FEAT_SM103_ALL)
#define TCG 1
#else
#define TCG 0
#endif

// =================== PTX helpers ===================
#if TCG
__device__ __forceinline__ uint elect_one_pred() {
    uint pred;
    asm volatile("{\n\t.reg .pred p;\n\telect.sync _|p, 0xFFFFFFFF;\n\t"
                 "selp.b32 %0, 1, 0, p;\n\t}" : "=r"(pred));
    return pred;
}
__device__ __forceinline__ uint smem_to_u32(const void* p) {
    uint a;
    asm("{ .reg .u64 t; cvta.to.shared.u64 t, %1; cvt.u32.u64 %0, t; }" : "=r"(a) : "l"(p));
    return a;
}
#define TCGEN05_ALLOC(smem_result_addr, nCols) \
    asm volatile("tcgen05.alloc.cta_group::1.sync.aligned.shared::cta.b32 [%0], %1;" \
        :: "r"((uint)(smem_result_addr)), "r"((uint)(nCols)) : "memory")
#define TCGEN05_DEALLOC(tmem_addr, nCols) \
    asm volatile("tcgen05.dealloc.cta_group::1.sync.aligned.b32 %0, %1;" \
        :: "r"(tmem_addr), "r"(nCols))
#define TCGEN05_RELINQUISH() \
    asm volatile("tcgen05.relinquish_alloc_permit.cta_group::1.sync.aligned;")
#define TCGEN05_WAIT_ST() asm volatile("tcgen05.wait::st.sync.aligned;" ::: "memory")
#define TCGEN05_WAIT_LD() asm volatile("tcgen05.wait::ld.sync.aligned;" ::: "memory")
#define TCGEN05_FENCE_AFTER() asm volatile("tcgen05.fence::after_thread_sync;" ::: "memory")
#define TCGEN05_FENCE_BEFORE() asm volatile("tcgen05.fence::before_thread_sync;" ::: "memory")
#define TCGEN05_COMMIT(mbar) \
    asm volatile("tcgen05.commit.cta_group::1.mbarrier::arrive::one.shared::cluster.b64 [%0];" \
        :: "r"((uint)(mbar)) : "memory")
#define MBARRIER_INIT(mbar, cnt) \
    asm volatile("mbarrier.init.shared.b64 [%0], %1;" :: "r"((uint)(mbar)), "r"((uint)(cnt)) : "memory")
#define MBARRIER_INVAL(mbar) \
    asm volatile("mbarrier.inval.shared.b64 [%0];" :: "r"((uint)(mbar)) : "memory")
#define MBARRIER_WAIT_PARITY(mbar, parity) do { \
    uint _m = (uint)(mbar), _p = (uint)(parity), _d; \
    asm volatile("{\n\t.reg .pred p;\n\t" \
        "mbarrier.try_wait.parity.acquire.cta.shared::cta.b64 p, [%1], %2;\n\t" \
        "selp.b32 %0, 1, 0, p;\n\t}" : "=r"(_d) : "r"(_m), "r"(_p) : "memory"); \
    if (!_d) { \
        asm volatile("{\n\t.reg .pred P1;\n\t" \
            "WAIT_LOOP_%=:\n\t" \
            "mbarrier.try_wait.parity.acquire.cta.shared::cta.b64 P1, [%0], %1, 0x989680;\n\t" \
            "@P1 bra.uni WAIT_DONE_%=;\n\t" \
            "bra.uni WAIT_LOOP_%=;\n\t" \
            "WAIT_DONE_%=:\n\t}" :: "r"(_m), "r"(_p) : "memory"); \
    } \
} while (0)
#define TCGEN05_MMA_F16(d_tmem, a_tmem, b_desc, idesc, enable_d) do { \
    uint _en = (enable_d) ? 1u : 0u; uint _z = 0u; \
    asm volatile("{\n\t.reg .pred p;\n\tsetp.ne.u32 p, %6, 0;\n\t" \
        "tcgen05.mma.cta_group::1.kind::f16 [%0], [%1], %2, %3, {%4, %4, %4, %4}, p;\n\t}" \
        :: "r"(d_tmem), "r"(a_tmem), "l"(b_desc), "r"(idesc), "r"(_z), "r"(_z), "r"(_en) \
        : "memory"); \
} while (0)
#define TCGEN05_ST_X16(tmem_addr, r) \
    asm volatile("tcgen05.st.sync.aligned.32x32b.x16.b32 [%0], " \
        "{%1,%2,%3,%4,%5,%6,%7,%8,%9,%10,%11,%12,%13,%14,%15,%16};" \
        :: "r"(tmem_addr), \
           "r"((r)[0]),"r"((r)[1]),"r"((r)[2]),"r"((r)[3]),"r"((r)[4]),"r"((r)[5]),"r"((r)[6]),"r"((r)[7]), \
           "r"((r)[8]),"r"((r)[9]),"r"((r)[10]),"r"((r)[11]),"r"((r)[12]),"r"((r)[13]),"r"((r)[14]),"r"((r)[15]) \
        : "memory")
#define TCGEN05_ST_X32(tmem_addr, r) \
    asm volatile("tcgen05.st.sync.aligned.32x32b.x32.b32 [%0], " \
        "{%1,%2,%3,%4,%5,%6,%7,%8,%9,%10,%11,%12,%13,%14,%15,%16," \
        " %17,%18,%19,%20,%21,%22,%23,%24,%25,%26,%27,%28,%29,%30,%31,%32};" \
        :: "r"(tmem_addr), \
           "r"((r)[0]),"r"((r)[1]),"r"((r)[2]),"r"((r)[3]),"r"((r)[4]),"r"((r)[5]),"r"((r)[6]),"r"((r)[7]), \
           "r"((r)[8]),"r"((r)[9]),"r"((r)[10]),"r"((r)[11]),"r"((r)[12]),"r"((r)[13]),"r"((r)[14]),"r"((r)[15]), \
           "r"((r)[16]),"r"((r)[17]),"r"((r)[18]),"r"((r)[19]),"r"((r)[20]),"r"((r)[21]),"r"((r)[22]),"r"((r)[23]), \
           "r"((r)[24]),"r"((r)[25]),"r"((r)[26]),"r"((r)[27]),"r"((r)[28]),"r"((r)[29]),"r"((r)[30]),"r"((r)[31]) \
        : "memory")
#define TCGEN05_LD_X32(r, tmem_addr) \
    asm volatile("tcgen05.ld.sync.aligned.32x32b.x32.b32 " \
        "{%0,%1,%2,%3,%4,%5,%6,%7,%8,%9,%10,%11,%12,%13,%14,%15," \
        " %16,%17,%18,%19,%20,%21,%22,%23,%24,%25,%26,%27,%28,%29,%30,%31}, [%32];" \
        : "=r"((r)[0]),"=r"((r)[1]),"=r"((r)[2]),"=r"((r)[3]),"=r"((r)[4]),"=r"((r)[5]),"=r"((r)[6]),"=r"((r)[7]), \
          "=r"((r)[8]),"=r"((r)[9]),"=r"((r)[10]),"=r"((r)[11]),"=r"((r)[12]),"=r"((r)[13]),"=r"((r)[14]),"=r"((r)[15]), \
          "=r"((r)[16]),"=r"((r)[17]),"=r"((r)[18]),"=r"((r)[19]),"=r"((r)[20]),"=r"((r)[21]),"=r"((r)[22]),"=r"((r)[23]), \
          "=r"((r)[24]),"=r"((r)[25]),"=r"((r)[26]),"=r"((r)[27]),"=r"((r)[28]),"=r"((r)[29]),"=r"((r)[30]),"=r"((r)[31]) \
        : "r"(tmem_addr))
#endif  // TCG

// SW128 smem descriptor (Blackwell, LBO=1, SBO=64) — verified constants
static constexpr uint64_t SMEM_DESC_BASE_SW128 =
    (uint64_t(2) << 61) | (uint64_t(1) << 46) | (uint64_t(64) << 32) | (uint64_t(1) << 16);
#define MAKE_SMEM_DESC(addr) (SMEM_DESC_BASE_SW128 | ((uint64_t)((addr) >> 4) & 0x3FFF))

// idesc kind::f16: dtype F32(1<<4) | atype BF16(1<<7) | btype BF16(1<<10) | (N/8)<<17 | (M/16)<<24
static constexpr uint IDESC2 = 0x490u | (8u  << 17) | (8u << 24);   // M=128, N=64
static constexpr uint IDESC3 = 0x490u | (16u << 17) | (8u << 24);   // M=128, N=128

// =================== static device scratch ===================
__device__ float g_wscale[4];
__device__ float g_w1q[32*3*3*3];
__device__ uint  g_w2f[4608];     // conv2 weights, legacy IMMA A-frag order (fallback path)
__device__ uint  g_w3f[18432];    // conv3 weights, legacy IMMA A-frag order (fallback path)
__device__ uint4 g_w2b[2560];     // conv2 weights bf16, SW128 blocked-atom layout (tcgen05)
__device__ uint4 g_w3b[9216];     // conv3 weights bf16, SW128 blocked-atom layout (tcgen05)
__device__ uint  g_wcp[10*32];
__device__ uint4 g_h1[32*112*112*32/16];
__device__ uint4 g_h2[32*56*56*64/16];
__device__ uint4 g_h3[32*28*28*128/16];

// ---------------- shared helpers ----------------
__device__ __forceinline__ void mma_s8(int* c, uint a0, uint a1, uint a2, uint a3,
                                       uint b0, uint b1) {
    asm volatile(
        "mma.sync.aligned.m16n8k32.row.col.s32.s8.s8.s32 "
        "{%0,%1,%2,%3}, {%4,%5,%6,%7}, {%8,%9}, {%0,%1,%2,%3};\n"
        : "+r"(c[0]), "+r"(c[1]), "+r"(c[2]), "+r"(c[3])
        : "r"(a0), "r"(a1), "r"(a2), "r"(a3), "r"(b0), "r"(b1));
}
// code(0..3) -> bf16 pair via byte_perm LUT
__device__ __forceinline__ void expand4(uint w, uint& lo, uint& hi) {
    const uint L = 0x40008000u;   // lo bytes of bf16(0..3)
    const uint H = 0x40403F00u;   // hi bytes of bf16(0..3)
    uint c0 = w & 3u, c1 = (w >> 8) & 3u, c2 = (w >> 16) & 3u, c3 = (w >> 24) & 3u;
    lo = __byte_perm(L, H, c0 * 0x11u + c1 * 0x1100u + 0x4040u);
    hi = __byte_perm(L, H, c2 * 0x11u + c3 * 0x1100u + 0x4040u);
}
__device__ __forceinline__ uint enc_tern(int q) {       // -1/0/1 -> bf16 bits
    return q > 0 ? 0x3F80u : (q < 0 ? 0xBF80u : 0u);
}
// byte offset in SW128 blocked-atom B tile: row=n (oc), col=k (bf16), N8 = N/8 atoms per k-block
__device__ __forceinline__ uint b_off(int n, int k, int N8) {
    uint off = (uint)((n >> 3) + (k >> 6) * N8) * 1024u + (uint)(n & 7) * 128u + (uint)(k & 63) * 2u;
    return off ^ ((off >> 3) & 0x70u);
}

// =================== kernel 0: per-tensor max-abs weight scales ===================
__global__ void k_scales(const float* __restrict__ w1, const float* __restrict__ w2,
                         const float* __restrict__ w3, const float* __restrict__ wc) {
    const float* ptrs[4] = {w1, w2, w3, wc};
    const int    ns[4]   = {864, 18432, 73728, 1280};
    int r = blockIdx.x;
    const float* w = ptrs[r];
    int n = ns[r];
    float m = 0.f;
    for (int i = threadIdx.x; i < n; i += blockDim.x) m = fmaxf(m, fabsf(w[i]));
    __shared__ float s[256];
    s[threadIdx.x] = m;
    __syncthreads();
    for (int o = 128; o > 0; o >>= 1) {
        if (threadIdx.x < o) s[threadIdx.x] = fmaxf(s[threadIdx.x], s[threadIdx.x + o]);
        __syncthreads();
    }
    if (threadIdx.x == 0) g_wscale[r] = fmaxf(s[0], 1e-8f);
}

// =================== kernel 1: quantize + pack weights (both encodings) ===================
__global__ void k_pack(const float* __restrict__ w1, const float* __restrict__ w2,
                       const float* __restrict__ w3, const float* __restrict__ wc) {
    int i = blockIdx.x * blockDim.x + threadIdx.x;
    if (i < 864) {
        float s = g_wscale[0];
        g_w1q[i] = rintf(__fdiv_rn(w1[i], s)) * s;
    } else if (i < 864 + 4608) {
        // conv2 IMMA A-frag
        int k = i - 864;
        float s = g_wscale[1];
        int e = k >> 2, r = k & 3;
        int lane = e & 31, tap = (e >> 5) % 9, m = e / 288;
        int oc  = m * 16 + (lane >> 2) + (r & 1) * 8;
        int ic0 = (r >> 1) * 16 + (lane & 3) * 4;
        int ty = tap / 3, tx = tap % 3;
        uint pk = 0;
        #pragma unroll
        for (int kk = 0; kk < 4; kk++) {
            int q = (int)rintf(__fdiv_rn(w2[((oc * 32 + ic0 + kk) * 3 + ty) * 3 + tx], s));
            pk |= ((uint)(unsigned char)(signed char)q) << (8 * kk);
        }
        g_w2f[k] = pk;
    } else if (i < 864 + 4608 + 18432) {
        // conv3 IMMA A-frag
        int k = i - (864 + 4608);
        float s = g_wscale[2];
        int e = k >> 2, r = k & 3;
        int lane = e & 31;
        int kc  = (e >> 5) & 1;
        int tap = (e >> 6) % 9;
        int m   = e / 576;
        int oc  = m * 16 + (lane >> 2) + (r & 1) * 8;
        int ic0 = kc * 32 + (r >> 1) * 16 + (lane & 3) * 4;
        int ty = tap / 3, tx = tap % 3;
        uint pk = 0;
        #pragma unroll
        for (int kk = 0; kk < 4; kk++) {
            int q = (int)rintf(__fdiv_rn(w3[((oc * 64 + ic0 + kk) * 3 + ty) * 3 + tx], s));
            pk |= ((uint)(unsigned char)(signed char)q) << (8 * kk);
        }
        g_w3f[k] = pk;
    } else if (i < 864 + 4608 + 18432 + 320) {
        int k = i - (864 + 4608 + 18432);
        float s = g_wscale[3];
        int oc = k / 32, j = k % 32;
        uint pk = 0;
        #pragma unroll
        for (int kk = 0; kk < 4; kk++) {
            int q = (int)rintf(__fdiv_rn(wc[oc * 128 + 4 * j + kk], s));
            pk |= ((uint)(unsigned char)(signed char)q) << (8 * kk);
        }
        g_wcp[k] = pk;
    } else if (i < 864 + 4608 + 18432 + 320 + 10240) {
        // conv2 bf16 SW128 (K2 = 288, padded to 320; N=64 -> 10240 uints)
        int idx = i - (864 + 4608 + 18432 + 320);
        float s = g_wscale[1];
        int oc = idx / 160, kp = idx % 160, k0 = 2 * kp;
        uint word = 0;
        #pragma unroll
        for (int h = 0; h < 2; h++) {
            int k = k0 + h;
            uint e = 0;
            if (k < 288) {
                int tap = k / 32, ic = k % 32, ty = tap / 3, tx = tap % 3;
                e = enc_tern((int)rintf(__fdiv_rn(w2[((oc * 32 + ic) * 3 + ty) * 3 + tx], s)));
            }
            word |= e << (16 * h);
        }
        ((uint*)g_w2b)[b_off(oc, k0, 8) >> 2] = word;
    } else if (i < 864 + 4608 + 18432 + 320 + 10240 + 36864) {
        // conv3 bf16 SW128 (K3 = 576, exact; N=128 -> 36864 uints)
        int idx = i - (864 + 4608 + 18432 + 320 + 10240);
        float s = g_wscale[2];
        int oc = idx / 288, kp = idx % 288, k0 = 2 * kp;
        uint word = 0;
        #pragma unroll
        for (int h = 0; h < 2; h++) {
            int k = k0 + h;
            int tap = k / 64, ic = k % 64, ty = tap / 3, tx = tap % 3;
            uint e = enc_tern((int)rintf(__fdiv_rn(w3[((oc * 64 + ic) * 3 + ty) * 3 + tx], s)));
            word |= e << (16 * h);
        }
        ((uint*)g_w3b)[b_off(oc, k0, 16) >> 2] = word;
    }
}

// =================== kernel 2: conv1 (fp32) + quant + pool ===================
__global__ __launch_bounds__(256) void k_conv1(const float* __restrict__ x,
                                               const float* __restrict__ a1) {
    __shared__ float s_in[3*34*34];
    __shared__ float s_w[864];
    int b  = blockIdx.z;
    int Y0 = blockIdx.y * 16, X0 = blockIdx.x * 16;

    for (int i = threadIdx.x; i < 864; i += 256) s_w[i] = g_w1q[i];
    for (int i = threadIdx.x; i < 3*34*34; i += 256) {
        int ic = i / 1156, rem = i % 1156, r = rem / 34, c = rem % 34;
        int gy = 2*Y0 - 1 + r, gx = 2*X0 - 1 + c;
        float v = 0.f;
        if ((unsigned)gy < 224u && (unsigned)gx < 224u)
            v = x[((b*3 + ic)*224 + gy)*224 + gx];
        s_in[i] = v;
    }
    __syncthreads();

    int sy = threadIdx.x >> 4, sx = threadIdx.x & 15;
    float p[3][4][4];
    #pragma unroll
    for (int ic = 0; ic < 3; ic++)
        #pragma unroll
        for (int u = 0; u < 4; u++)
            #pragma unroll
            for (int v = 0; v < 4; v++)
                p[ic][u][v] = s_in[ic*1156 + (2*sy + u)*34 + (2*sx + v)];

    float alpha = a1[0];
    float qs = __fdiv_rn(alpha, 3.0f);
    uint* h1u = (uint*)g_h1;
    int pixbase = ((b*112 + (Y0 + sy))*112 + (X0 + sx)) * 8;

    #pragma unroll 1
    for (int og = 0; og < 8; og++) {
        uint pk = 0;
        #pragma unroll
        for (int oo = 0; oo < 4; oo++) {
            int oc = og*4 + oo;
            float a00 = 0.f, a01 = 0.f, a10 = 0.f, a11 = 0.f;
            #pragma unroll
            for (int ic = 0; ic < 3; ic++)
                #pragma unroll
                for (int ty = 0; ty < 3; ty++)
                    #pragma unroll
                    for (int tx = 0; tx < 3; tx++) {
                        float w = s_w[oc*27 + ic*9 + ty*3 + tx];
                        a00 = fmaf(w, p[ic][ty  ][tx  ], a00);
                        a01 = fmaf(w, p[ic][ty  ][tx+1], a01);
                        a10 = fmaf(w, p[ic][ty+1][tx  ], a10);
                        a11 = fmaf(w, p[ic][ty+1][tx+1], a11);
                    }
            float v = fmaxf(fmaxf(a00, a01), fmaxf(a10, a11));
            float y = fminf(fmaxf(v, 0.f), alpha);
            uint code = (uint)(int)rintf(__fdiv_rn(y, qs));
            pk |= code << (8*oo);
        }
        h1u[pixbase + og] = pk;
    }
}

// =================== fallback kernels (legacy IMMA) — empty in sm_103a pass ===================
__global__ __launch_bounds__(256) void k_mma2(const float* __restrict__ a_prev,
                                              const float* __restrict__ a_cur) {
#if !TCG && defined(__CUDA_ARCH__)
    __shared__ uint4 s4[4*114*3];
    uint* sw = (uint*)s4;
    int Y = blockIdx.x, b = blockIdx.y;
    int tid = threadIdx.x;

    for (int j = tid; j < 912; j += 256) {
        int row = j / 228, rem = j % 228, pix = rem >> 1, half = rem & 1;
        int gy = 2*Y - 1 + row, gx = pix - 1;
        uint4 v = make_uint4(0u,0u,0u,0u);
        if ((unsigned)gy < 112u && (unsigned)gx < 112u)
            v = g_h1[((b*112 + gy)*112 + gx)*2 + half];
        s4[(row*114 + pix)*3 + half] = v;
    }
    __syncthreads();

    int warp = tid >> 5, lane = tid & 31;
    int xh = warp & 1, m = warp >> 1;
    int g = lane >> 2, q = lane & 3;

    int acc[2][7][4];
    #pragma unroll
    for (int y = 0; y < 2; y++)
        #pragma unroll
        for (int nt = 0; nt < 7; nt++)
            #pragma unroll
            for (int k = 0; k < 4; k++) acc[y][nt][k] = 0;

    const uint4* wf = (const uint4*)g_w2f;
    #pragma unroll 1
    for (int tap = 0; tap < 9; tap++) {
        uint4 wv = wf[(m*9 + tap)*32 + lane];
        int ty = tap / 3, tx = tap % 3;
        #pragma unroll
        for (int y = 0; y < 2; y++) {
            int rowbase = (y + ty)*114;
            #pragma unroll
            for (int nt = 0; nt < 7; nt++) {
                int pix = xh*56 + nt*8 + g + tx;
                int w0 = (rowbase + pix)*12 + q;
                uint b0 = sw[w0], b1 = sw[w0 + 4];
                mma_s8(acc[y][nt], wv.x, wv.y, wv.z, wv.w, b0, b1);
            }
        }
    }

    float scale = g_wscale[1] * __fdiv_rn(a_prev[0], 3.0f);
    float alpha = a_cur[0];
    float qs = __fdiv_rn(alpha, 3.0f);
    char* out = (char*)g_h2;
    #pragma unroll
    for (int nt = 0; nt < 7; nt++) {
        int v0 = max(max(acc[0][nt][0], acc[0][nt][1]), max(acc[1][nt][0], acc[1][nt][1]));
        int v1 = max(max(acc[0][nt][2], acc[0][nt][3]), max(acc[1][nt][2], acc[1][nt][3]));
        int X = xh*28 + nt*4 + q;
        int base = ((b*56 + Y)*56 + X)*64 + m*16 + g;
        float y0 = fminf(fmaxf(scale*(float)v0, 0.f), alpha);
        float y1 = fminf(fmaxf(scale*(float)v1, 0.f), alpha);
        out[base]     = (char)(int)rintf(__fdiv_rn(y0, qs));
        out[base + 8] = (char)(int)rintf(__fdiv_rn(y1, qs));
    }
#endif
}

__global__ __launch_bounds__(256) void k_mma3(const float* __restrict__ a_prev,
                                              const float* __restrict__ a_cur) {
#if !TCG && defined(__CUDA_ARCH__)
    __shared__ uint4 s4[4*58*5];
    uint* sw = (uint*)s4;
    int Y = blockIdx.x, b = blockIdx.y;
    int tid = threadIdx.x;

    for (int j = tid; j < 928; j += 256) {
        int row = j / 232, rem = j % 232, pix = rem >> 2, qq = rem & 3;
        int gy = 2*Y - 1 + row, gx = pix - 1;
        uint4 v = make_uint4(0u,0u,0u,0u);
        if ((unsigned)gy < 56u && (unsigned)gx < 56u)
            v = g_h2[((b*56 + gy)*56 + gx)*4 + qq];
        s4[(row*58 + pix)*5 + qq] = v;
    }
    __syncthreads();

    int warp = tid >> 5, lane = tid & 31;
    int m = warp;
    int g = lane >> 2, q = lane & 3;

    int acc[2][7][4];
    #pragma unroll
    for (int y = 0; y < 2; y++)
        #pragma unroll
        for (int nt = 0; nt < 7; nt++)
            #pragma unroll
            for (int k = 0; k < 4; k++) acc[y][nt][k] = 0;

    const uint4* wf = (const uint4*)g_w3f;
    #pragma unroll 1
    for (int tap = 0; tap < 9; tap++) {
        int ty = tap / 3, tx = tap % 3;
        #pragma unroll
        for (int kc = 0; kc < 2; kc++) {
            uint4 wv = wf[((m*9 + tap)*2 + kc)*32 + lane];
            #pragma unroll
            for (int y = 0; y < 2; y++) {
                int rowbase = (y + ty)*58;
                #pragma unroll
                for (int nt = 0; nt < 7; nt++) {
                    int pix = nt*8 + g + tx;
                    int w0 = (rowbase + pix)*20 + kc*8 + q;
                    uint b0 = sw[w0], b1 = sw[w0 + 4];
                    mma_s8(acc[y][nt], wv.x, wv.y, wv.z, wv.w, b0, b1);
                }
            }
        }
    }

    float scale = g_wscale[2] * __fdiv_rn(a_prev[0], 3.0f);
    float alpha = a_cur[0];
    float qs = __fdiv_rn(alpha, 3.0f);
    char* out = (char*)g_h3;
    #pragma unroll
    for (int nt = 0; nt < 7; nt++) {
        int v0 = max(max(acc[0][nt][0], acc[0][nt][1]), max(acc[1][nt][0], acc[1][nt][1]));
        int v1 = max(max(acc[0][nt][2], acc[0][nt][3]), max(acc[1][nt][2], acc[1][nt][3]));
        int X = nt*4 + q;
        int base = ((b*28 + Y)*28 + X)*128 + m*16 + g;
        float y0 = fminf(fmaxf(scale*(float)v0, 0.f), alpha);
        float y1 = fminf(fmaxf(scale*(float)v1, 0.f), alpha);
        out[base]     = (char)(int)rintf(__fdiv_rn(y0, qs));
        out[base + 8] = (char)(int)rintf(__fdiv_rn(y1, qs));
    }
#endif
}

// =================== tcgen05 kernels — empty in non-a pass ===================
// conv2: M=128 px (1 pooled row × 64 pre-pool x), N=64 oc, K=288. Persistent, 1 CTA/SM.
__global__ __launch_bounds__(128) void k_t2(const float* __restrict__ a_prev,
                                            const float* __restrict__ a_cur) {
#if TCG
    extern __shared__ char smem[];
    uint sb = smem_to_u32(smem);
    int tid = threadIdx.x, wid = tid >> 5, lane = tid & 31;
    uint brel = ((sb + 8512u + 1023u) & ~1023u) - sb;
    uint* Bp = (uint*)(smem + brel);
    char* codes = smem + 64;

    for (int i = tid; i < 10240; i += 128) Bp[i] = ((const uint*)g_w2b)[i];

    if (wid == 0) { TCGEN05_ALLOC(sb + 0, 256); TCGEN05_RELINQUISH(); }
    if (tid == 0) MBARRIER_INIT(sb + 8, 1);
    __syncthreads();
    uint tmem;
    asm volatile("ld.shared.b32 %0, [%1];" : "=r"(tmem) : "r"(sb + 0));
    uint64_t bdesc0 = MAKE_SMEM_DESC(sb + brel);
    uint warp_off = (uint)wid << 21;

    float scale = g_wscale[1] * __fdiv_rn(a_prev[0], 3.0f);
    float alpha = a_cur[0];
    float qs = __fdiv_rn(alpha, 3.0f);

    int ph = 0;
    for (int t = blockIdx.x; t < 3584; t += 148) {
        int b = t / 112, r2 = t % 112, Yp = r2 >> 1, X0 = (r2 & 1) * 48;
        __syncthreads();
        for (int i = tid; i < 528; i += 128) {
            int r = i / 132, rem = i % 132, cc = rem >> 1, half = rem & 1;
            int gy = 2*Yp - 1 + r, gx = X0 - 1 + cc;
            uint4 v = make_uint4(0u,0u,0u,0u);
            if ((unsigned)gy < 112u && (unsigned)gx < 112u)
                v = g_h1[((b*112 + gy)*112 + gx)*2 + half];
            *(uint4*)(codes + (r*66 + cc)*32 + half*16) = v;
        }
        __syncthreads();
        {
            int u = tid >> 2, c = tid & 3;
            int r_l = c >> 1, x_l = 2*u + (c & 1);
            #pragma unroll 1
            for (int tap = 0; tap < 9; tap++) {
                int ty = tap / 3, tx = tap % 3;
                const uint* src = (const uint*)(codes + ((r_l + ty)*66 + (x_l + tx))*32);
                uint rg[16];
                #pragma unroll
                for (int j = 0; j < 8; j++) expand4(src[j], rg[2*j], rg[2*j+1]);
                TCGEN05_ST_X16(tmem + tap*16 + warp_off, rg);
            }
            TCGEN05_WAIT_ST();
        }
        __syncthreads();
        if (wid == 0) {
            if (elect_one_pred()) {
                #pragma unroll 1
                for (int s = 0; s < 18; s++) {
                    uint64_t bd = bdesc0 + (uint64_t)((s & 3)*2 + (s >> 2)*512);
                    TCGEN05_MMA_F16(tmem + 144, tmem + s*8, bd, IDESC2, s > 0);
                }
                TCGEN05_COMMIT(sb + 8);
            }
        }
        MBARRIER_WAIT_PARITY(sb + 8, ph);
        ph ^= 1;
        TCGEN05_FENCE_AFTER();
        {
            uint d[64];
            TCGEN05_LD_X32(d,      tmem + 144);
            TCGEN05_LD_X32(d + 32, tmem + 144 + 32);
            TCGEN05_WAIT_LD();
            TCGEN05_FENCE_BEFORE();
            uint pk[16];
            #pragma unroll
            for (int j = 0; j < 16; j++) pk[j] = 0;
            #pragma unroll
            for (int j = 0; j < 64; j++) {
                float v = __uint_as_float(d[j]);
                v = fmaxf(v, __shfl_xor_sync(0xffffffffu, v, 1));
                v = fmaxf(v, __shfl_xor_sync(0xffffffffu, v, 2));
                float y = fminf(fmaxf(scale * v, 0.f), alpha);
                uint code = (uint)(int)rintf(__fdiv_rn(y, qs));
                pk[j >> 2] |= code << (8*(j & 3));
            }
            if ((lane & 3) == 0) {
                int u = (wid*32 + lane) >> 2;
                int Xp = (X0 >> 1) + u;
                uint4* dst = (uint4*)((char*)g_h2 + ((size_t)((b*56 + Yp)*56 + Xp)) * 64);
                dst[0] = make_uint4(pk[0], pk[1], pk[2], pk[3]);
                dst[1] = make_uint4(pk[4], pk[5], pk[6], pk[7]);
                dst[2] = make_uint4(pk[8], pk[9], pk[10], pk[11]);
                dst[3] = make_uint4(pk[12], pk[13], pk[14], pk[15]);
            }
        }
    }
    __syncthreads();
    if (tid == 0) MBARRIER_INVAL(sb + 8);
    __syncthreads();
    if (wid == 0) TCGEN05_DEALLOC(tmem, 256);
#endif
}

// conv3: M=128 px (112 valid), N=128 oc, K=576. Persistent, 1 CTA/SM.
__global__ __launch_bounds__(128) void k_t3(const float* __restrict__ a_prev,
                                            const float* __restrict__ a_cur) {
#if TCG
    extern __shared__ char smem[];
    uint sb = smem_to_u32(smem);
    int tid = threadIdx.x, wid = tid >> 5, lane = tid & 31;
    uint brel = ((sb + 14912u + 1023u) & ~1023u) - sb;
    uint4* Bp = (uint4*)(smem + brel);
    char* codes = smem + 64;

    for (int i = tid; i < 9216; i += 128) Bp[i] = g_w3b[i];

    if (wid == 0) { TCGEN05_ALLOC(sb + 0, 512); TCGEN05_RELINQUISH(); }
    if (tid == 0) MBARRIER_INIT(sb + 8, 1);
    __syncthreads();
    uint tmem;
    asm volatile("ld.shared.b32 %0, [%1];" : "=r"(tmem) : "r"(sb + 0));
    uint64_t bdesc0 = MAKE_SMEM_DESC(sb + brel);
    uint warp_off = (uint)wid << 21;

    float scale = g_wscale[2] * __fdiv_rn(a_prev[0], 3.0f);
    float alpha = a_cur[0];
    float qs = __fdiv_rn(alpha, 3.0f);

    int ph = 0;
    for (int t = blockIdx.x; t < 896; t += 148) {
        int b = t / 28, Yp = t % 28;
        __syncthreads();
        for (int i = tid; i < 928; i += 128) {
            int r = i / 232, rem = i % 232, cc = rem >> 2, qq = rem & 3;
            int gy = 2*Yp - 1 + r, gx = cc - 1;
            uint4 v = make_uint4(0u,0u,0u,0u);
            if ((unsigned)gy < 56u && (unsigned)gx < 56u)
                v = g_h2[((b*56 + gy)*56 + gx)*4 + qq];
            *(uint4*)(codes + (r*58 + cc)*64 + qq*16) = v;
        }
        __syncthreads();
        {
            int u = tid >> 2, c = tid & 3;
            if (u > 27) u = 27;
            int r_l = c >> 1, x_l = 2*u + (c & 1);
            #pragma unroll 1
            for (int tap = 0; tap < 9; tap++) {
                int ty = tap / 3, tx = tap % 3;
                const uint* src = (const uint*)(codes + ((r_l + ty)*58 + (x_l + tx))*64);
                uint rg[32];
                #pragma unroll
                for (int j = 0; j < 16; j++) expand4(src[j], rg[2*j], rg[2*j+1]);
                TCGEN05_ST_X32(tmem + tap*32 + warp_off, rg);
            }
            TCGEN05_WAIT_ST();
        }
        __syncthreads();
        if (wid == 0) {
            if (elect_one_pred()) {
                #pragma unroll 1
                for (int s = 0; s < 36; s++) {
                    uint64_t bd = bdesc0 + (uint64_t)((s & 3)*2 + (s >> 2)*1024);
                    TCGEN05_MMA_F16(tmem + 288, tmem + s*8, bd, IDESC3, s > 0);
                }
                TCGEN05_COMMIT(sb + 8);
            }
        }
        MBARRIER_WAIT_PARITY(sb + 8, ph);
        ph ^= 1;
        TCGEN05_FENCE_AFTER();
        {
            int u = (wid*32 + lane) >> 2;
            bool act = ((lane & 3) == 0) && (u < 28);
            size_t bytebase = ((size_t)((b*28 + Yp)*28 + (u < 28 ? u : 0))) * 128;
            #pragma unroll 1
            for (int ch = 0; ch < 4; ch++) {
                uint d[32];
                TCGEN05_LD_X32(d, tmem + 288 + 32*ch);
                TCGEN05_WAIT_LD();
                uint pk[8];
                #pragma unroll
                for (int j = 0; j < 8; j++) pk[j] = 0;
                #pragma unroll
                for (int j = 0; j < 32; j++) {
                    float v = __uint_as_float(d[j]);
                    v = fmaxf(v, __shfl_xor_sync(0xffffffffu, v, 1));
                    v = fmaxf(v, __shfl_xor_sync(0xffffffffu, v, 2));
                    float y = fminf(fmaxf(scale * v, 0.f), alpha);
                    uint code = (uint)(int)rintf(__fdiv_rn(y, qs));
                    pk[j >> 2] |= code << (8*(j & 3));
                }
                if (act) {
                    uint4* dst = (uint4*)((char*)g_h3 + bytebase + 32*ch);
                    dst[0] = make_uint4(pk[0], pk[1], pk[2], pk[3]);
                    dst[1] = make_uint4(pk[4], pk[5], pk[6], pk[7]);
                }
            }
            TCGEN05_FENCE_BEFORE();
        }
    }
    __syncthreads();
    if (tid == 0) MBARRIER_INVAL(sb + 8);
    __syncthreads();
    if (wid == 0) TCGEN05_DEALLOC(tmem, 512);
#endif
}

// =================== kernel 5: global amax pool + 1x1 ternary classifier ===================
__global__ void k_cls(const float* __restrict__ a3, float* __restrict__ out) {
    __shared__ uint s_part[4][32];
    __shared__ uint s_max[32];
    int b = blockIdx.x, t = threadIdx.x;
    const uint* h3u = (const uint*)g_h3;
    int quarter = t >> 5, ci = t & 31;
    uint m = 0;
    int p0 = quarter * 196;
    for (int p = p0; p < p0 + 196; p++)
        m = __vmaxu4(m, h3u[(b*784 + p)*32 + ci]);
    s_part[quarter][ci] = m;
    __syncthreads();
    if (t < 32)
        s_max[t] = __vmaxu4(__vmaxu4(s_part[0][t], s_part[1][t]),
                            __vmaxu4(s_part[2][t], s_part[3][t]));
    __syncthreads();
    if (t < 10) {
        int acc = 0;
        #pragma unroll
        for (int j = 0; j < 32; j++)
            acc = __dp4a((int)s_max[j], (int)g_wcp[t*32 + j], acc);
        float scale = g_wscale[3] * __fdiv_rn(a3[0], 3.0f);
        out[b*10 + t] = scale * (float)acc;
    }
}

// =================== launch ===================
extern "C" void kernel_launch(void* const* d_in, const int* in_sizes, int n_in,
                              void* d_out, int out_size) {
    const float* x  = (const float*)d_in[0];
    const float* w1 = (const float*)d_in[1];
    const float* w2 = (const float*)d_in[2];
    const float* w3 = (const float*)d_in[3];
    const float* wc = (const float*)d_in[4];
    const float* a1 = (const float*)d_in[5];
    const float* a2 = (const float*)d_in[6];
    const float* a3 = (const float*)d_in[7];
    float* out = (float*)d_out;

    const int SMEM_T2 = 8512 + 1024 + 40960;     // 50496
    const int SMEM_T3 = 14912 + 1024 + 147456;   // 163392
    cudaFuncSetAttribute(k_t2, cudaFuncAttributeMaxDynamicSharedMemorySize, SMEM_T2);
    cudaFuncSetAttribute(k_t3, cudaFuncAttributeMaxDynamicSharedMemorySize, SMEM_T3);

    k_scales<<<4, 256>>>(w1, w2, w3, wc);
    k_pack<<<(71328 + 255)/256, 256>>>(w1, w2, w3, wc);
    k_conv1<<<dim3(7, 7, 32), 256>>>(x, a1);        // 112x112x32 pooled codes

    // conv2/conv3: exactly one of each pair has a non-empty body per target.
    k_mma2<<<dim3(56, 32), 256>>>(a1, a2);          // fallback (non-a pass)
    k_t2<<<148, 128, SMEM_T2>>>(a1, a2);            // tcgen05 (sm_103a pass)
    k_mma3<<<dim3(28, 32), 256>>>(a2, a3);          // fallback
    k_t3<<<148, 128, SMEM_T3>>>(a2, a3);            // tcgen05

    k_cls<<<32, 128>>>(a3, out);
}